// round 9
// baseline (speedup 1.0000x reference)
#include <cuda_runtime.h>
#include <cuda_bf16.h>
#include <math.h>

#define Bb 4
#define Nn 256
#define Dd 128
#define NODES (Bb*Nn)
#define MAXN (1.0f - 4e-3f)

// ---------------- scratch (__device__ globals; allocation-free) ----------------
__device__ float g_h[NODES*Dd];           // h after HypLinear
__device__ float g_s[NODES];              // ||h||^2
__device__ float g_r[NODES*Dd];           // h @ W1b^T
__device__ float g_sup[NODES*16];         // per-jtile partial sums of w_ij * U_ij
__device__ float g_part[16*NODES*Dd];     // per-jtile partials of (wV) @ H   (8 MB)

__device__ __forceinline__ float artanhf_c(float x) {
    x = fminf(fmaxf(x, -1.0f + 1e-7f), 1.0f - 1e-7f);
    return 0.5f * logf((1.0f + x) / (1.0f - x));
}

__device__ __forceinline__ float tanhap(float x) {
    float y;
    asm("tanh.approx.f32 %0, %1;" : "=f"(y) : "f"(x));
    return y;
}

__device__ __forceinline__ float dot4(float4 a, float4 b) {
    return fmaf(a.x, b.x, fmaf(a.y, b.y, fmaf(a.z, b.z, a.w * b.w)));
}

// deterministic warp-wide sum, broadcast (fixed butterfly order)
__device__ __forceinline__ float warpSum(float v) {
    #pragma unroll
    for (int o = 16; o > 0; o >>= 1) v += __shfl_xor_sync(0xffffffffu, v, o);
    return v;
}

// Stage a 128x128 weight matrix row-major into smem, pitch 33 float4 (coalesced, conflict-free).
__device__ __forceinline__ void stageW(float4* Ws4, const float* __restrict__ src,
                                       int rstride4, int coff4, int t, int nthreads) {
    const float4* s4 = (const float4*)src;
    for (int idx = t; idx < 4096; idx += nthreads) {
        int c = idx >> 5, m4 = idx & 31;
        Ws4[c*33 + m4] = s4[c*rstride4 + coff4 + m4];
    }
}

// Dual-node permuted-output 128x128 matvec: lane produces channels {l,l+32,l+64,l+96}
// for BOTH nodes; each weight float4 is loaded once and feeds 2 nodes (8 indep chains).
__device__ __forceinline__ void matvecP2(const float4* __restrict__ Ws4,
                                         const float4* __restrict__ vA,
                                         const float4* __restrict__ vB, int lane,
                                         float oA[4], float oB[4]) {
    float a0=0.f,a1=0.f,a2=0.f,a3=0.f, b0=0.f,b1=0.f,b2=0.f,b3=0.f;
    const float4* w0p = Ws4 + lane*33;
    const float4* w1p = Ws4 + (lane+32)*33;
    const float4* w2p = Ws4 + (lane+64)*33;
    const float4* w3p = Ws4 + (lane+96)*33;
    #pragma unroll 8
    for (int m4 = 0; m4 < 32; m4++) {
        float4 w0 = w0p[m4], w1 = w1p[m4], w2 = w2p[m4], w3 = w3p[m4];
        float4 va = vA[m4], vb = vB[m4];
        a0 += dot4(w0, va); b0 += dot4(w0, vb);
        a1 += dot4(w1, va); b1 += dot4(w1, vb);
        a2 += dot4(w2, va); b2 += dot4(w2, vb);
        a3 += dot4(w3, va); b3 += dot4(w3, vb);
    }
    oA[0]=a0; oA[1]=a1; oA[2]=a2; oA[3]=a3;
    oB[0]=b0; oB[1]=b1; oB[2]=b2; oB[3]=b3;
}

// ======================= K1: HypLinear + R (2 warps x 2 nodes, two-phase restage) =======================
__global__ void k1_hyplinear(const float* __restrict__ x, const float* __restrict__ W,
                             const float* __restrict__ b_lin, const float* __restrict__ att_w1) {
    extern __shared__ float4 dsm4[];
    float4* Ws4 = dsm4;            // 128*33
    float4* vs4 = dsm4 + 128*33;   // 4 nodes * 32
    int t = threadIdx.x, wid = t >> 5, lane = t & 31;

    stageW(Ws4, W, 32, 0, t, 64);

    // hyperbolic bias: proj(expmap0(b_lin)) on permuted channels {l+32k}
    float bk[4];
    #pragma unroll
    for (int k = 0; k < 4; k++) bk[k] = b_lin[lane + 32*k];
    float bn2 = warpSum(bk[0]*bk[0] + bk[1]*bk[1] + bk[2]*bk[2] + bk[3]*bk[3]);
    float bn  = fmaxf(sqrtf(bn2), 1e-15f);
    float tb  = tanhf(bn);
    float hb[4];
    #pragma unroll
    for (int k = 0; k < 4; k++) hb[k] = tb * bk[k] / bn;
    float hbn = fabsf(tb);
    if (hbn > MAXN) { float s = MAXN/hbn;
        #pragma unroll
        for (int k = 0; k < 4; k++) hb[k] *= s; }
    float y2 = (hbn > MAXN) ? MAXN*MAXN : hbn*hbn;
    __syncthreads();

    int node0 = blockIdx.x * 4 + wid * 2;
    float4* vA = vs4 + (wid*2)*32;
    float4* vB = vs4 + (wid*2 + 1)*32;
    float* vAf = (float*)vA;
    float* vBf = (float*)vB;

    float4 xA = ((const float4*)(x + node0*Dd))[lane];
    float4 xB = ((const float4*)(x + (node0+1)*Dd))[lane];
    vA[lane] = xA; vB[lane] = xB;
    __syncwarp();
    float xn2_[2];
    xn2_[0] = warpSum(dot4(xA, xA));
    xn2_[1] = warpSum(dot4(xB, xB));
    float mxA[4], mxB[4];
    matvecP2(Ws4, vA, vB, lane, mxA, mxB);

    float hh[2][4]; float hs2_[2];
    #pragma unroll
    for (int nn = 0; nn < 2; nn++) {
        float* mx = nn ? mxB : mxA;
        float mxn2 = warpSum(mx[0]*mx[0] + mx[1]*mx[1] + mx[2]*mx[2] + mx[3]*mx[3]);
        float res[4]; float rn;
        if (mxn2 == 0.0f) {
            res[0]=res[1]=res[2]=res[3]=0.f; rn = 0.0f;
        } else {
            float xn  = fmaxf(sqrtf(xn2_[nn]), 1e-15f);
            float mxn = fmaxf(sqrtf(mxn2), 1e-15f);
            float arg = mxn / xn * artanhf_c(xn);
            float tt  = tanhf(arg);
            float sc  = tt / mxn;
            #pragma unroll
            for (int k = 0; k < 4; k++) res[k] = sc * mx[k];
            rn = fabsf(tt);
        }
        float rnc = fmaxf(rn, 1e-15f);
        if (rnc > MAXN) { float s = MAXN/rnc;
            #pragma unroll
            for (int k = 0; k < 4; k++) res[k] *= s; }
        float x2 = (rnc > MAXN) ? MAXN*MAXN : rn*rn;
        // mobius_add(res, hb)
        float xy = warpSum(res[0]*hb[0] + res[1]*hb[1] + res[2]*hb[2] + res[3]*hb[3]);
        float A  = 1.0f + 2.0f*xy + y2;
        float Bc = 1.0f - x2;
        float den = fmaxf(1.0f + 2.0f*xy + x2*y2, 1e-15f);
        float id = 1.0f/den;
        float h[4];
        #pragma unroll
        for (int k = 0; k < 4; k++) h[k] = (A*res[k] + Bc*hb[k]) * id;
        // proj
        float hn2 = warpSum(h[0]*h[0] + h[1]*h[1] + h[2]*h[2] + h[3]*h[3]);
        float hn  = fmaxf(sqrtf(hn2), 1e-15f);
        float hs2;
        if (hn > MAXN) { float s = MAXN/hn;
            #pragma unroll
            for (int k = 0; k < 4; k++) h[k] *= s;
            hs2 = MAXN*MAXN; }
        else hs2 = hn2;
        #pragma unroll
        for (int k = 0; k < 4; k++) { hh[nn][k] = h[k]; g_h[(node0+nn)*Dd + lane + 32*k] = h[k]; }
        hs2_[nn] = hs2;
    }
    if (lane == 0) { g_s[node0] = hs2_[0]; g_s[node0+1] = hs2_[1]; }

    // ---- phase 2: restage W1b, compute R = h @ W1b^T ----
    __syncthreads();                        // all warps done with Ws4 and vs4
    stageW(Ws4, att_w1, 64, 32, t, 64);     // W1b = att_w1[:, Dd:2Dd]
    #pragma unroll
    for (int k = 0; k < 4; k++) { vAf[lane + 32*k] = hh[0][k]; vBf[lane + 32*k] = hh[1][k]; }
    __syncthreads();
    float rA[4], rB[4];
    matvecP2(Ws4, vA, vB, lane, rA, rB);
    #pragma unroll
    for (int k = 0; k < 4; k++) {
        g_r[node0*Dd + lane + 32*k]     = rA[k];
        g_r[(node0+1)*Dd + lane + 32*k] = rB[k];
    }
}

// ======================= K3: pairwise attention + fused partial aggregation =======================
__global__ void k_pair(const float* __restrict__ mask, const float* __restrict__ att_b1,
                       const float* __restrict__ att_w2, const float* __restrict__ att_b2) {
    __shared__ float4 hi4[16*33], hj4[16*33], ri4[16*33], rj4[16*33];
    __shared__ float4 w2s4[32], b1s4[32];
    __shared__ float ssi[16], ssj[16];
    __shared__ float redsmU[16*17], redsmV[16*17];

    int b  = blockIdx.z;
    int i0 = blockIdx.y * 16;
    int j0 = blockIdx.x * 16;
    int base = b * Nn;
    int tid = threadIdx.x;   // 256

    for (int idx = tid; idx < 16*32; idx += 256) {
        int row = idx >> 5, k4 = idx & 31;
        hi4[row*33 + k4] = ((const float4*)(g_h + (base + i0 + row)*Dd))[k4];
        hj4[row*33 + k4] = ((const float4*)(g_h + (base + j0 + row)*Dd))[k4];
        ri4[row*33 + k4] = ((const float4*)(g_r + (base + i0 + row)*Dd))[k4];
        rj4[row*33 + k4] = ((const float4*)(g_r + (base + j0 + row)*Dd))[k4];
    }
    if (tid < 16) { ssi[tid] = g_s[base + i0 + tid]; ssj[tid] = g_s[base + j0 + tid]; }
    if (tid >= 64 && tid < 96)  w2s4[tid - 64] = ((const float4*)att_w2)[tid - 64];
    if (tid >= 96 && tid < 128) b1s4[tid - 96] = ((const float4*)att_b1)[tid - 96];
    int ti = tid >> 4, tj = tid & 15;
    float mval = mask[(base + i0 + ti)*Nn + j0 + tj];
    float b2v  = __ldg(att_b2);
    __syncthreads();

    // gram <h_i, h_j>
    float g = 0.f;
    #pragma unroll
    for (int k4 = 0; k4 < 32; k4++) {
        float4 a = hi4[ti*33 + k4];
        float4 c = hj4[tj*33 + k4];
        g = fmaf(a.x, c.x, fmaf(a.y, c.y, fmaf(a.z, c.z, fmaf(a.w, c.w, g))));
    }
    float si = ssi[ti], sj = ssj[tj];

    float A   = 1.0f - 2.0f*g + sj;
    float Bc  = 1.0f - si;
    float den = fmaxf(1.0f - 2.0f*g + si*sj, 1e-15f);
    float p = -A / den, q = Bc / den;
    float sn2 = fmaf(p*p, si, fmaf(2.0f*p*q, g, q*q*sj));
    float sn  = fmaxf(sqrtf(fmaxf(sn2, 0.0f)), 1e-15f);
    float fac = fmaxf(1.0f - si, 1e-15f) * artanhf_c(sn) / sn;
    float U = fac * p, V = fac * q;

    // attention logit: e = sum_k w2[k]*silu(b1[k]+U*r_i[k]+V*r_j[k]); silu via tanh.approx
    float e = 0.f;
    #pragma unroll
    for (int k4 = 0; k4 < 32; k4++) {
        float4 rv = ri4[ti*33 + k4];
        float4 sv = rj4[tj*33 + k4];
        float4 bv = b1s4[k4];
        float4 wv = w2s4[k4];
        {
            float a = fmaf(U, rv.x, fmaf(V, sv.x, bv.x));
            float s = 0.5f * fmaf(a, tanhap(0.5f*a), a);
            e = fmaf(wv.x, s, e);
        }
        {
            float a = fmaf(U, rv.y, fmaf(V, sv.y, bv.y));
            float s = 0.5f * fmaf(a, tanhap(0.5f*a), a);
            e = fmaf(wv.y, s, e);
        }
        {
            float a = fmaf(U, rv.z, fmaf(V, sv.z, bv.z));
            float s = 0.5f * fmaf(a, tanhap(0.5f*a), a);
            e = fmaf(wv.z, s, e);
        }
        {
            float a = fmaf(U, rv.w, fmaf(V, sv.w, bv.w));
            float s = 0.5f * fmaf(a, tanhap(0.5f*a), a);
            e = fmaf(wv.w, s, e);
        }
    }
    float w = __fdividef(1.0f, 1.0f + __expf(-(e + b2v))) * mval;

    redsmU[ti*17 + tj] = w * U;
    redsmV[ti*17 + tj] = w * V;
    __syncthreads();
    if (tj == 0) {
        float s = 0.f;
        #pragma unroll
        for (int x2i = 0; x2i < 16; x2i++) s += redsmU[ti*17 + x2i];
        g_sup[(base + i0 + ti)*16 + blockIdx.x] = s;
    }

    // fused partial aggregation: part[ti][c] = sum_tj (wV)[ti][tj] * h_j[tj][c]
    float4 acc0 = make_float4(0.f,0.f,0.f,0.f);
    float4 acc1 = make_float4(0.f,0.f,0.f,0.f);
    #pragma unroll
    for (int j2 = 0; j2 < 16; j2++) {
        float m = redsmV[ti*17 + j2];
        float4 hA = hj4[j2*33 + tj];
        float4 hB = hj4[j2*33 + 16 + tj];
        acc0.x = fmaf(m, hA.x, acc0.x); acc0.y = fmaf(m, hA.y, acc0.y);
        acc0.z = fmaf(m, hA.z, acc0.z); acc0.w = fmaf(m, hA.w, acc0.w);
        acc1.x = fmaf(m, hB.x, acc1.x); acc1.y = fmaf(m, hB.y, acc1.y);
        acc1.z = fmaf(m, hB.z, acc1.z); acc1.w = fmaf(m, hB.w, acc1.w);
    }
    float4* gp = (float4*)(g_part + ((size_t)blockIdx.x*NODES + base + i0 + ti)*Dd);
    gp[tj]      = acc0;
    gp[16 + tj] = acc1;
}

// ======================= K5: combine + MLP + expmap + HypAct (2 warps x 2 nodes) =======================
__global__ void k5_mlp(const float* __restrict__ mlp_w1, const float* __restrict__ mlp_b1,
                       const float* __restrict__ mlp_w2, const float* __restrict__ mlp_b2,
                       float* __restrict__ out) {
    extern __shared__ float4 dsm4[];
    float4* Ws4 = dsm4;
    float4* vs4 = dsm4 + 128*33;
    int t = threadIdx.x, wid = t >> 5, lane = t & 31;

    stageW(Ws4, mlp_w1, 64, 32, t, 64);   // second-half columns of (d,2d)
    __syncthreads();

    int node0 = blockIdx.x * 4 + wid * 2;
    float4* vA = vs4 + (wid*2)*32;
    float4* vB = vs4 + (wid*2 + 1)*32;
    float* vAf = (float*)vA;
    float* vBf = (float*)vB;

    // combine 16 j-tile partials + diagonal term, per node
    #pragma unroll
    for (int nn = 0; nn < 2; nn++) {
        int node = node0 + nn;
        float4 sv = make_float4(0.f,0.f,0.f,0.f);
        #pragma unroll
        for (int jt = 0; jt < 16; jt++) {
            float4 pv = ((const float4*)(g_part + ((size_t)jt*NODES + node)*Dd))[lane];
            sv.x += pv.x; sv.y += pv.y; sv.z += pv.z; sv.w += pv.w;
        }
        float su = 0.f;
        #pragma unroll
        for (int jt = 0; jt < 16; jt++) su += g_sup[node*16 + jt];
        float4 h4 = ((const float4*)(g_h + node*Dd))[lane];
        float4 r = make_float4(fmaf(su, h4.x, sv.x), fmaf(su, h4.y, sv.y),
                               fmaf(su, h4.z, sv.z), fmaf(su, h4.w, sv.w));
        if (nn == 0) vA[lane] = r; else vB[lane] = r;
    }
    __syncwarp();
    float aA[4], aB[4];
    matvecP2(Ws4, vA, vB, lane, aA, aB);
    float saA[4], saB[4];
    #pragma unroll
    for (int k = 0; k < 4; k++) {
        float b1v = mlp_b1[lane + 32*k];
        float av = aA[k] + b1v;
        saA[k] = av / (1.0f + __expf(-av));
        float bv = aB[k] + b1v;
        saB[k] = bv / (1.0f + __expf(-bv));
    }

    // ---- phase 2: restage W2 ----
    __syncthreads();
    stageW(Ws4, mlp_w2, 32, 0, t, 64);
    #pragma unroll
    for (int k = 0; k < 4; k++) { vAf[lane + 32*k] = saA[k]; vBf[lane + 32*k] = saB[k]; }
    __syncthreads();
    float oA[4], oB[4];
    matvecP2(Ws4, vA, vB, lane, oA, oB);

    #pragma unroll
    for (int nn = 0; nn < 2; nn++) {
        int node = node0 + nn;
        float o[4], h[4];
        #pragma unroll
        for (int k = 0; k < 4; k++) {
            o[k] = (nn ? oB[k] : oA[k]) + mlp_b2[lane + 32*k];
            h[k] = g_h[node*Dd + lane + 32*k];
        }
        float si = g_s[node];
        // expmap(o, h)
        float un2 = warpSum(o[0]*o[0] + o[1]*o[1] + o[2]*o[2] + o[3]*o[3]);
        float un  = fmaxf(sqrtf(un2), 1e-15f);
        float lam = 2.0f / fmaxf(1.0f - si, 1e-15f);
        float tt  = tanhf(0.5f * lam * un);
        float sc  = tt / un;
        float sec[4];
        #pragma unroll
        for (int k = 0; k < 4; k++) sec[k] = sc * o[k];
        float y2  = tt * tt;
        // mobius_add(h, sec)
        float xy = warpSum(h[0]*sec[0] + h[1]*sec[1] + h[2]*sec[2] + h[3]*sec[3]);
        float A   = 1.0f + 2.0f*xy + y2;
        float Bc  = 1.0f - si;
        float den = fmaxf(1.0f + 2.0f*xy + si*y2, 1e-15f);
        float id  = 1.0f/den;
        float ov[4];
        #pragma unroll
        for (int k = 0; k < 4; k++) ov[k] = (A*h[k] + Bc*sec[k]) * id;
        // proj
        float on2 = warpSum(ov[0]*ov[0] + ov[1]*ov[1] + ov[2]*ov[2] + ov[3]*ov[3]);
        float on  = fmaxf(sqrtf(on2), 1e-15f);
        float pn2;
        if (on > MAXN) { float s = MAXN/on;
            #pragma unroll
            for (int k = 0; k < 4; k++) ov[k] *= s;
            pn2 = MAXN*MAXN; }
        else pn2 = on2;
        // HypAct: silu(logmap0(ov)) -> expmap0 -> proj
        float pn  = fmaxf(sqrtf(pn2), 1e-15f);
        float lsc = artanhf_c(pn) / pn;
        float xt[4];
        #pragma unroll
        for (int k = 0; k < 4; k++) {
            float v = lsc * ov[k];
            xt[k] = v / (1.0f + __expf(-v));
        }
        float un3 = warpSum(xt[0]*xt[0] + xt[1]*xt[1] + xt[2]*xt[2] + xt[3]*xt[3]);
        float u3n = fmaxf(sqrtf(un3), 1e-15f);
        float t3  = tanhf(u3n);
        float rsc = t3 / u3n;
        float rn  = fmaxf(fabsf(t3), 1e-15f);
        float fin = (rn > MAXN) ? rsc * (MAXN/rn) : rsc;
        #pragma unroll
        for (int k = 0; k < 4; k++) out[node*Dd + lane + 32*k] = fin * xt[k];
    }
}

// ======================= launch =======================
extern "C" void kernel_launch(void* const* d_in, const int* in_sizes, int n_in,
                              void* d_out, int out_size) {
    const float* x      = (const float*)d_in[0];
    const float* mask   = (const float*)d_in[1];
    const float* W      = (const float*)d_in[2];
    const float* b_lin  = (const float*)d_in[3];
    const float* att_w1 = (const float*)d_in[4];
    const float* att_b1 = (const float*)d_in[5];
    const float* att_w2 = (const float*)d_in[6];
    const float* att_b2 = (const float*)d_in[7];
    const float* mlp_w1 = (const float*)d_in[8];
    const float* mlp_b1 = (const float*)d_in[9];
    const float* mlp_w2 = (const float*)d_in[10];
    const float* mlp_b2 = (const float*)d_in[11];
    float* out = (float*)d_out;

    const int smemW = (128*33 + 4*32) * (int)sizeof(float4);   // 69,632 B
    cudaFuncSetAttribute(k1_hyplinear, cudaFuncAttributeMaxDynamicSharedMemorySize, smemW);
    cudaFuncSetAttribute(k5_mlp,       cudaFuncAttributeMaxDynamicSharedMemorySize, smemW);

    k1_hyplinear<<<NODES/4, 64, smemW>>>(x, W, b_lin, att_w1);
    dim3 g3(Nn/16, Nn/16, Bb);
    k_pair<<<g3, 256>>>(mask, att_b1, att_w2, att_b2);
    k5_mlp<<<NODES/4, 64, smemW>>>(mlp_w1, mlp_b1, mlp_w2, mlp_b2, out);
}

// round 10
// speedup vs baseline: 1.1622x; 1.1622x over previous
#include <cuda_runtime.h>
#include <cuda_bf16.h>
#include <math.h>

#define Bb 4
#define Nn 256
#define Dd 128
#define NODES (Bb*Nn)
#define MAXN (1.0f - 4e-3f)

// ---------------- scratch (__device__ globals; allocation-free) ----------------
__device__ float g_h[NODES*Dd];           // h after HypLinear
__device__ float g_s[NODES];              // ||h||^2
__device__ float g_r[NODES*Dd];           // h @ W1b^T
__device__ float g_sup[NODES*16];         // per-jtile partial sums of w_ij * U_ij
__device__ float g_part[16*NODES*Dd];     // per-jtile partials of (wV) @ H   (8 MB)

__device__ __forceinline__ float artanhf_c(float x) {
    x = fminf(fmaxf(x, -1.0f + 1e-7f), 1.0f - 1e-7f);
    return 0.5f * logf((1.0f + x) / (1.0f - x));
}

__device__ __forceinline__ float tanhap(float x) {
    float y;
    asm("tanh.approx.f32 %0, %1;" : "=f"(y) : "f"(x));
    return y;
}

__device__ __forceinline__ float dot4(float4 a, float4 b) {
    return fmaf(a.x, b.x, fmaf(a.y, b.y, fmaf(a.z, b.z, a.w * b.w)));
}

// deterministic warp-wide sum, broadcast (fixed butterfly order)
__device__ __forceinline__ float warpSum(float v) {
    #pragma unroll
    for (int o = 16; o > 0; o >>= 1) v += __shfl_xor_sync(0xffffffffu, v, o);
    return v;
}

// Stage a 128x128 weight matrix row-major into smem, pitch 33 float4 (coalesced, conflict-free).
__device__ __forceinline__ void stageW(float4* Ws4, const float* __restrict__ src,
                                       int rstride4, int coff4, int t, int nthreads) {
    const float4* s4 = (const float4*)src;
    for (int idx = t; idx < 4096; idx += nthreads) {
        int c = idx >> 5, m4 = idx & 31;
        Ws4[c*33 + m4] = s4[c*rstride4 + coff4 + m4];
    }
}

// Permuted-output 128x128 matvec: lane produces channels {l, l+32, l+64, l+96}.
// 2 accumulators per channel; fully unrolled so ptxas can hoist LDS loads.
__device__ __forceinline__ void matvecP(const float4* __restrict__ Ws4,
                                        const float4* __restrict__ v, int lane,
                                        float out[4]) {
    float a0 = 0.f, a1 = 0.f, a2 = 0.f, a3 = 0.f;
    float b0 = 0.f, b1 = 0.f, b2 = 0.f, b3 = 0.f;
    const float4* w0p = Ws4 + lane*33;
    const float4* w1p = Ws4 + (lane+32)*33;
    const float4* w2p = Ws4 + (lane+64)*33;
    const float4* w3p = Ws4 + (lane+96)*33;
    #pragma unroll
    for (int m4 = 0; m4 < 32; m4 += 2) {
        float4 vm = v[m4];
        a0 += dot4(w0p[m4], vm);
        a1 += dot4(w1p[m4], vm);
        a2 += dot4(w2p[m4], vm);
        a3 += dot4(w3p[m4], vm);
        float4 vn = v[m4+1];
        b0 += dot4(w0p[m4+1], vn);
        b1 += dot4(w1p[m4+1], vn);
        b2 += dot4(w2p[m4+1], vn);
        b3 += dot4(w3p[m4+1], vn);
    }
    out[0] = a0 + b0; out[1] = a1 + b1; out[2] = a2 + b2; out[3] = a3 + b3;
}

// ======================= K1: HypLinear + R = H @ W1b^T (4 warps, two-phase restage) =======================
__global__ void __launch_bounds__(128, 1)
k1_hyplinear(const float* __restrict__ x, const float* __restrict__ W,
             const float* __restrict__ b_lin, const float* __restrict__ att_w1) {
    extern __shared__ float4 dsm4[];
    float4* Ws4 = dsm4;            // 128*33
    float4* vs4 = dsm4 + 128*33;   // 4*32
    int t = threadIdx.x, wid = t >> 5, lane = t & 31;

    stageW(Ws4, W, 32, 0, t, 128);

    // hyperbolic bias: proj(expmap0(b_lin)) on permuted channels {l+32k}
    float bk[4];
    #pragma unroll
    for (int k = 0; k < 4; k++) bk[k] = b_lin[lane + 32*k];
    float bn2 = warpSum(bk[0]*bk[0] + bk[1]*bk[1] + bk[2]*bk[2] + bk[3]*bk[3]);
    float bn  = fmaxf(sqrtf(bn2), 1e-15f);
    float tb  = tanhf(bn);
    float hb[4];
    #pragma unroll
    for (int k = 0; k < 4; k++) hb[k] = tb * bk[k] / bn;
    float hbn = fabsf(tb);
    if (hbn > MAXN) { float s = MAXN/hbn;
        #pragma unroll
        for (int k = 0; k < 4; k++) hb[k] *= s; }
    float y2 = (hbn > MAXN) ? MAXN*MAXN : hbn*hbn;
    __syncthreads();

    int node = blockIdx.x * 4 + wid;
    float4* vw = vs4 + wid*32;
    float* vwf = (float*)vw;

    float4 x4 = ((const float4*)(x + node*Dd))[lane];
    vw[lane] = x4;
    __syncwarp();
    float xn2 = warpSum(dot4(x4, x4));
    float mx[4];
    matvecP(Ws4, vw, lane, mx);
    float mxn2 = warpSum(mx[0]*mx[0] + mx[1]*mx[1] + mx[2]*mx[2] + mx[3]*mx[3]);
    float res[4]; float rn;
    if (mxn2 == 0.0f) {
        res[0]=res[1]=res[2]=res[3]=0.f; rn = 0.0f;
    } else {
        float xn  = fmaxf(sqrtf(xn2), 1e-15f);
        float mxn = fmaxf(sqrtf(mxn2), 1e-15f);
        float arg = mxn / xn * artanhf_c(xn);
        float tt  = tanhf(arg);
        float sc  = tt / mxn;
        #pragma unroll
        for (int k = 0; k < 4; k++) res[k] = sc * mx[k];
        rn = fabsf(tt);
    }
    float rnc = fmaxf(rn, 1e-15f);
    if (rnc > MAXN) { float s = MAXN/rnc;
        #pragma unroll
        for (int k = 0; k < 4; k++) res[k] *= s; }
    float x2 = (rnc > MAXN) ? MAXN*MAXN : rn*rn;
    // mobius_add(res, hb)
    float xy = warpSum(res[0]*hb[0] + res[1]*hb[1] + res[2]*hb[2] + res[3]*hb[3]);
    float A  = 1.0f + 2.0f*xy + y2;
    float Bc = 1.0f - x2;
    float den = fmaxf(1.0f + 2.0f*xy + x2*y2, 1e-15f);
    float id = 1.0f/den;
    float h[4];
    #pragma unroll
    for (int k = 0; k < 4; k++) h[k] = (A*res[k] + Bc*hb[k]) * id;
    // proj
    float hn2 = warpSum(h[0]*h[0] + h[1]*h[1] + h[2]*h[2] + h[3]*h[3]);
    float hn  = fmaxf(sqrtf(hn2), 1e-15f);
    float hs2;
    if (hn > MAXN) { float s = MAXN/hn;
        #pragma unroll
        for (int k = 0; k < 4; k++) h[k] *= s;
        hs2 = MAXN*MAXN; }
    else hs2 = hn2;
    #pragma unroll
    for (int k = 0; k < 4; k++) g_h[node*Dd + lane + 32*k] = h[k];
    if (lane == 0) g_s[node] = hs2;

    // ---- phase 2: restage W1b, compute R = h @ W1b^T ----
    __syncthreads();                        // all warps done with Ws4 (and vw)
    stageW(Ws4, att_w1, 64, 32, t, 128);    // W1b = att_w1[:, Dd:2Dd]
    #pragma unroll
    for (int k = 0; k < 4; k++) vwf[lane + 32*k] = h[k];   // standard order, conflict-free
    __syncthreads();
    float r[4];
    matvecP(Ws4, vw, lane, r);
    #pragma unroll
    for (int k = 0; k < 4; k++) g_r[node*Dd + lane + 32*k] = r[k];
}

// ======================= K3: pairwise attention + fused partial aggregation =======================
__global__ void k_pair(const float* __restrict__ mask, const float* __restrict__ att_b1,
                       const float* __restrict__ att_w2, const float* __restrict__ att_b2) {
    __shared__ float4 hi4[16*33], hj4[16*33], ri4[16*33], rj4[16*33];
    __shared__ float4 w2s4[32], b1s4[32];
    __shared__ float ssi[16], ssj[16];
    __shared__ float redsmU[16*17], redsmV[16*17];

    int b  = blockIdx.z;
    int i0 = blockIdx.y * 16;
    int j0 = blockIdx.x * 16;
    int base = b * Nn;
    int tid = threadIdx.x;   // 256

    for (int idx = tid; idx < 16*32; idx += 256) {
        int row = idx >> 5, k4 = idx & 31;
        hi4[row*33 + k4] = ((const float4*)(g_h + (base + i0 + row)*Dd))[k4];
        hj4[row*33 + k4] = ((const float4*)(g_h + (base + j0 + row)*Dd))[k4];
        ri4[row*33 + k4] = ((const float4*)(g_r + (base + i0 + row)*Dd))[k4];
        rj4[row*33 + k4] = ((const float4*)(g_r + (base + j0 + row)*Dd))[k4];
    }
    if (tid < 16) { ssi[tid] = g_s[base + i0 + tid]; ssj[tid] = g_s[base + j0 + tid]; }
    if (tid >= 64 && tid < 96)  w2s4[tid - 64] = ((const float4*)att_w2)[tid - 64];
    if (tid >= 96 && tid < 128) {
        float4 bv = ((const float4*)att_b1)[tid - 96];     // store b1/2 for halved silu
        b1s4[tid - 96] = make_float4(0.5f*bv.x, 0.5f*bv.y, 0.5f*bv.z, 0.5f*bv.w);
    }
    int ti = tid >> 4, tj = tid & 15;
    float mval = mask[(base + i0 + ti)*Nn + j0 + tj];
    float b2v  = __ldg(att_b2);
    __syncthreads();

    // gram <h_i, h_j>
    float g = 0.f;
    #pragma unroll
    for (int k4 = 0; k4 < 32; k4++) {
        float4 a = hi4[ti*33 + k4];
        float4 c = hj4[tj*33 + k4];
        g = fmaf(a.x, c.x, fmaf(a.y, c.y, fmaf(a.z, c.z, fmaf(a.w, c.w, g))));
    }
    float si = ssi[ti], sj = ssj[tj];

    float A   = 1.0f - 2.0f*g + sj;
    float Bc  = 1.0f - si;
    float den = fmaxf(1.0f - 2.0f*g + si*sj, 1e-15f);
    float p = -A / den, q = Bc / den;
    float sn2 = fmaf(p*p, si, fmaf(2.0f*p*q, g, q*q*sj));
    float sn  = fmaxf(sqrtf(fmaxf(sn2, 0.0f)), 1e-15f);
    float fac = fmaxf(1.0f - si, 1e-15f) * artanhf_c(sn) / sn;
    float U = fac * p, V = fac * q;
    float U2 = 0.5f * U, V2 = 0.5f * V;

    // attention logit: e = sum_k w2[k]*silu(a_k); with a2 = a/2 built from halved
    // coefficients, silu(a) = a2*(1 + tanh(a2)) = fmaf(a2, tanh(a2), a2).
    float e = 0.f;
    #pragma unroll
    for (int k4 = 0; k4 < 32; k4++) {
        float4 rv = ri4[ti*33 + k4];
        float4 sv = rj4[tj*33 + k4];
        float4 bv = b1s4[k4];
        float4 wv = w2s4[k4];
        {
            float a2 = fmaf(U2, rv.x, fmaf(V2, sv.x, bv.x));
            float s = fmaf(a2, tanhap(a2), a2);
            e = fmaf(wv.x, s, e);
        }
        {
            float a2 = fmaf(U2, rv.y, fmaf(V2, sv.y, bv.y));
            float s = fmaf(a2, tanhap(a2), a2);
            e = fmaf(wv.y, s, e);
        }
        {
            float a2 = fmaf(U2, rv.z, fmaf(V2, sv.z, bv.z));
            float s = fmaf(a2, tanhap(a2), a2);
            e = fmaf(wv.z, s, e);
        }
        {
            float a2 = fmaf(U2, rv.w, fmaf(V2, sv.w, bv.w));
            float s = fmaf(a2, tanhap(a2), a2);
            e = fmaf(wv.w, s, e);
        }
    }
    float w = __fdividef(1.0f, 1.0f + __expf(-(e + b2v))) * mval;

    redsmU[ti*17 + tj] = w * U;
    redsmV[ti*17 + tj] = w * V;
    __syncthreads();
    if (tj == 0) {
        float s = 0.f;
        #pragma unroll
        for (int x2i = 0; x2i < 16; x2i++) s += redsmU[ti*17 + x2i];
        g_sup[(base + i0 + ti)*16 + blockIdx.x] = s;
    }

    // fused partial aggregation: part[ti][c] = sum_tj (wV)[ti][tj] * h_j[tj][c]
    float4 acc0 = make_float4(0.f,0.f,0.f,0.f);
    float4 acc1 = make_float4(0.f,0.f,0.f,0.f);
    #pragma unroll
    for (int j2 = 0; j2 < 16; j2++) {
        float m = redsmV[ti*17 + j2];
        float4 hA = hj4[j2*33 + tj];
        float4 hB = hj4[j2*33 + 16 + tj];
        acc0.x = fmaf(m, hA.x, acc0.x); acc0.y = fmaf(m, hA.y, acc0.y);
        acc0.z = fmaf(m, hA.z, acc0.z); acc0.w = fmaf(m, hA.w, acc0.w);
        acc1.x = fmaf(m, hB.x, acc1.x); acc1.y = fmaf(m, hB.y, acc1.y);
        acc1.z = fmaf(m, hB.z, acc1.z); acc1.w = fmaf(m, hB.w, acc1.w);
    }
    float4* gp = (float4*)(g_part + ((size_t)blockIdx.x*NODES + base + i0 + ti)*Dd);
    gp[tj]      = acc0;
    gp[16 + tj] = acc1;
}

// ======================= K5: combine + node MLP + expmap + HypAct (4 warps, two-phase restage) =======================
__global__ void __launch_bounds__(128, 1)
k5_mlp(const float* __restrict__ mlp_w1, const float* __restrict__ mlp_b1,
       const float* __restrict__ mlp_w2, const float* __restrict__ mlp_b2,
       float* __restrict__ out) {
    extern __shared__ float4 dsm4[];
    float4* Ws4 = dsm4;
    float4* vs4 = dsm4 + 128*33;
    int t = threadIdx.x, wid = t >> 5, lane = t & 31;

    stageW(Ws4, mlp_w1, 64, 32, t, 128);   // second-half columns of (d,2d)
    __syncthreads();

    int node = blockIdx.x * 4 + wid;
    float4* vw = vs4 + wid*32;
    float* vwf = (float*)vw;

    // combine 16 j-tile partials + diagonal term (standard channel order)
    float4 sv = make_float4(0.f,0.f,0.f,0.f);
    #pragma unroll
    for (int jt = 0; jt < 16; jt++) {
        float4 pv = ((const float4*)(g_part + ((size_t)jt*NODES + node)*Dd))[lane];
        sv.x += pv.x; sv.y += pv.y; sv.z += pv.z; sv.w += pv.w;
    }
    float su = 0.f;
    #pragma unroll
    for (int jt = 0; jt < 16; jt++) su += g_sup[node*16 + jt];
    float4 h4 = ((const float4*)(g_h + node*Dd))[lane];
    vw[lane] = make_float4(fmaf(su, h4.x, sv.x), fmaf(su, h4.y, sv.y),
                           fmaf(su, h4.z, sv.z), fmaf(su, h4.w, sv.w));
    __syncwarp();
    float a[4];
    matvecP(Ws4, vw, lane, a);
    float sa[4];
    #pragma unroll
    for (int k = 0; k < 4; k++) {
        float av = a[k] + mlp_b1[lane + 32*k];
        sa[k] = av / (1.0f + __expf(-av));   // silu accurate
    }

    // ---- phase 2: restage W2 ----
    __syncthreads();
    stageW(Ws4, mlp_w2, 32, 0, t, 128);
    #pragma unroll
    for (int k = 0; k < 4; k++) vwf[lane + 32*k] = sa[k];
    __syncthreads();
    float o[4];
    matvecP(Ws4, vw, lane, o);
    float h[4];
    #pragma unroll
    for (int k = 0; k < 4; k++) {
        o[k] += mlp_b2[lane + 32*k];
        h[k] = g_h[node*Dd + lane + 32*k];
    }

    float si = g_s[node];
    // expmap(o, h)
    float un2 = warpSum(o[0]*o[0] + o[1]*o[1] + o[2]*o[2] + o[3]*o[3]);
    float un  = fmaxf(sqrtf(un2), 1e-15f);
    float lam = 2.0f / fmaxf(1.0f - si, 1e-15f);
    float tt  = tanhf(0.5f * lam * un);
    float sc  = tt / un;
    float sec[4];
    #pragma unroll
    for (int k = 0; k < 4; k++) sec[k] = sc * o[k];
    float y2  = tt * tt;
    // mobius_add(h, sec)
    float xy = warpSum(h[0]*sec[0] + h[1]*sec[1] + h[2]*sec[2] + h[3]*sec[3]);
    float A   = 1.0f + 2.0f*xy + y2;
    float Bc  = 1.0f - si;
    float den = fmaxf(1.0f + 2.0f*xy + si*y2, 1e-15f);
    float id  = 1.0f/den;
    float ov[4];
    #pragma unroll
    for (int k = 0; k < 4; k++) ov[k] = (A*h[k] + Bc*sec[k]) * id;
    // proj
    float on2 = warpSum(ov[0]*ov[0] + ov[1]*ov[1] + ov[2]*ov[2] + ov[3]*ov[3]);
    float on  = fmaxf(sqrtf(on2), 1e-15f);
    float pn2;
    if (on > MAXN) { float s = MAXN/on;
        #pragma unroll
        for (int k = 0; k < 4; k++) ov[k] *= s;
        pn2 = MAXN*MAXN; }
    else pn2 = on2;
    // HypAct: silu(logmap0(ov)) -> expmap0 -> proj
    float pn  = fmaxf(sqrtf(pn2), 1e-15f);
    float lsc = artanhf_c(pn) / pn;
    float xt[4];
    #pragma unroll
    for (int k = 0; k < 4; k++) {
        float v = lsc * ov[k];
        xt[k] = v / (1.0f + __expf(-v));
    }
    float un3 = warpSum(xt[0]*xt[0] + xt[1]*xt[1] + xt[2]*xt[2] + xt[3]*xt[3]);
    float u3n = fmaxf(sqrtf(un3), 1e-15f);
    float t3  = tanhf(u3n);
    float rsc = t3 / u3n;
    float rn  = fmaxf(fabsf(t3), 1e-15f);
    float fin = (rn > MAXN) ? rsc * (MAXN/rn) : rsc;
    #pragma unroll
    for (int k = 0; k < 4; k++) out[node*Dd + lane + 32*k] = fin * xt[k];
}

// ======================= launch =======================
extern "C" void kernel_launch(void* const* d_in, const int* in_sizes, int n_in,
                              void* d_out, int out_size) {
    const float* x      = (const float*)d_in[0];
    const float* mask   = (const float*)d_in[1];
    const float* W      = (const float*)d_in[2];
    const float* b_lin  = (const float*)d_in[3];
    const float* att_w1 = (const float*)d_in[4];
    const float* att_b1 = (const float*)d_in[5];
    const float* att_w2 = (const float*)d_in[6];
    const float* att_b2 = (const float*)d_in[7];
    const float* mlp_w1 = (const float*)d_in[8];
    const float* mlp_b1 = (const float*)d_in[9];
    const float* mlp_w2 = (const float*)d_in[10];
    const float* mlp_b2 = (const float*)d_in[11];
    float* out = (float*)d_out;

    const int smemW = (128*33 + 4*32) * (int)sizeof(float4);   // 69,632 B
    cudaFuncSetAttribute(k1_hyplinear, cudaFuncAttributeMaxDynamicSharedMemorySize, smemW);
    cudaFuncSetAttribute(k5_mlp,       cudaFuncAttributeMaxDynamicSharedMemorySize, smemW);

    k1_hyplinear<<<NODES/4, 128, smemW>>>(x, W, b_lin, att_w1);
    dim3 g3(Nn/16, Nn/16, Bb);
    k_pair<<<g3, 256>>>(mask, att_b1, att_w2, att_b2);
    k5_mlp<<<NODES/4, 128, smemW>>>(mlp_w1, mlp_b1, mlp_w2, mlp_b2, out);
}